// round 12
// baseline (speedup 1.0000x reference)
#include <cuda_runtime.h>
#include <cuda_bf16.h>
#include <cfloat>
#include <cstdint>

// Problem constants
#define NUM_EMBED 512
#define EMBED_DIM 64
#define N_TOKENS  131072            // 32 * 64 * 64
#define DECAY     0.99f
#define ONE_MINUS_DECAY 0.01f
#define EPS       1e-5f
#define COMMIT_COST 0.25f

// Output layout (float elements), tuple order:
// (loss[1], out[8388608], perplexity[1], encodings[131072*512],
//  new_embedding[512*64], cluster[512], new_ema_w[512*64])
#define OFF_LOSS   0
#define OFF_OUT    1
#define OFF_PERP   8388609
#define OFF_ENC    8388610
#define OFF_NEMB   75497474ll
#define OFF_CLUST  75530242ll
#define OFF_EMAW   75530754ll

// Scratch (no allocations allowed -> device globals).
// INVARIANT: g_counts/g_loss/g_dw are zero at kernel_launch entry.
// Zero-initialized at module load; phase2a/2b re-zero them after
// consuming, so the invariant holds across graph replays.
__device__ float               g_counts[NUM_EMBED];
__device__ __align__(16) float g_dw[NUM_EMBED * EMBED_DIM];
__device__ float               g_en2[NUM_EMBED];
__device__ float               g_cls[NUM_EMBED];
__device__ float               g_loss;

typedef unsigned long long ull;

// ---- f32x2 packed-math helpers (sm_100+; PTX-only) ----
__device__ __forceinline__ ull fma2(ull a, ull b, ull c) {
    ull d;
    asm("fma.rn.f32x2 %0, %1, %2, %3;" : "=l"(d) : "l"(a), "l"(b), "l"(c));
    return d;
}
__device__ __forceinline__ ull add2(ull a, ull b) {
    ull d;
    asm("add.rn.f32x2 %0, %1, %2;" : "=l"(d) : "l"(a), "l"(b));
    return d;
}
__device__ __forceinline__ ull pack2(float lo, float hi) {
    ull d;
    asm("mov.b64 %0, {%1, %2};" : "=l"(d) : "f"(lo), "f"(hi));
    return d;
}
__device__ __forceinline__ float2 unpack2(ull v) {
    float2 r;
    asm("mov.b64 {%0, %1}, %2;" : "=f"(r.x), "=f"(r.y) : "l"(v));
    return r;
}
__device__ __forceinline__ void lds_v2_u64(ull& a, ull& b, unsigned addr) {
    asm("ld.shared.v2.u64 {%0, %1}, [%2];" : "=l"(a), "=l"(b) : "r"(addr));
}
__device__ __forceinline__ void red_add_v4(float* p, float a, float b, float c, float d) {
    asm volatile("red.global.add.v4.f32 [%0], {%1,%2,%3,%4};"
                 :: "l"(p), "f"(a), "f"(b), "f"(c), "f"(d) : "memory");
}

// ============================================================
// Phase 0: ||e||^2 only. 1 block x 512 threads.
// NOTE: expression kept VERBATIM from the passing rounds — en2
// rounding is argmin-tie-critical; do not "improve" this.
// ============================================================
__global__ void vq_phase0(const float* __restrict__ emb) {
    int tid = threadIdx.x;
    const float2* ep = reinterpret_cast<const float2*>(emb + tid * EMBED_DIM);
    float s = 0.0f;
#pragma unroll
    for (int j = 0; j < 32; ++j) {
        float2 v = ep[j];
        s += v.x * v.x + v.y * v.y;
    }
    g_en2[tid] = s;
}

// ============================================================
// Phase 1: fused argmin + quantize + out + encodings + counts + dw + loss.
// 512 blocks x 256 threads, one token per thread.
// __launch_bounds__(256, 1): 255-reg budget so ptxas can hoist the
// shared-memory code loads ahead of the FFMA2 chains (at (256,2) the
// 128-reg cap forced just-in-time LDS -> exposed 29-cyc latency).
// Distance arithmetic kept VERBATIM (bit-exact) from the passing round.
// ============================================================
__global__ void __launch_bounds__(256, 1)
vq_phase1(const float* __restrict__ x,
          const float* __restrict__ emb,
          float* __restrict__ dout) {
    __shared__ float es[128 * EMBED_DIM];   // 32 KB code chunk
    __shared__ float en2s[128];
    __shared__ float red[256];

    const int tid   = threadIdx.x;
    const int tbase = blockIdx.x << 8;            // 256 tokens per block
    const int n     = tbase >> 12;                // batch index
    const int hw    = (tbase & 4095) + tid;       // spatial pos of this token

    float* out_main = dout + OFF_OUT;
    float* out_enc  = dout + OFF_ENC;

    // Coalesced zero of this block's 256 contiguous encodings rows (512 KB),
    // issued FIRST so the store drain overlaps the fma-bound distance loop.
    // OFF_ENC is only 8-byte aligned -> float2.
    {
        float2* ez = reinterpret_cast<float2*>(out_enc + (size_t)tbase * NUM_EMBED);
        float2 z2 = make_float2(0.0f, 0.0f);
#pragma unroll 8
        for (int i = tid; i < 256 * NUM_EMBED / 2; i += 256) ez[i] = z2;
    }

    const float* xp = x + ((size_t)n << 18) + hw; // n*64*4096 + hw

    // Load this token's 64 features, packed as f32x2 dim pairs.
    ull xv[32];
#pragma unroll
    for (int j = 0; j < 32; ++j)
        xv[j] = pack2(xp[(2 * j) << 12], xp[(2 * j + 1) << 12]);

    const unsigned sbase = (unsigned)__cvta_generic_to_shared(es);

    float best = FLT_MAX;
    int   bi   = 0;

    for (int ch = 0; ch < 4; ++ch) {
        __syncthreads();
        {   // cooperative load of 128 codes (8192 floats) + norms
            const float4* src = reinterpret_cast<const float4*>(emb) + ch * 2048;
            float4* dst = reinterpret_cast<float4*>(es);
#pragma unroll
            for (int i = 0; i < 8; ++i) dst[tid + i * 256] = src[tid + i * 256];
            if (tid < 128) en2s[tid] = g_en2[ch * 128 + tid];
        }
        __syncthreads();

#pragma unroll 2
        for (int e = 0; e < 128; ++e) {
            unsigned ad = sbase + e * (EMBED_DIM * 4);
            ull a0 = 0, a1 = 0;
#pragma unroll
            for (int j = 0; j < 16; ++j) {
                ull e01, e23;
                lds_v2_u64(e01, e23, ad + j * 16);
                a0 = fma2(xv[2 * j],     e01, a0);
                a1 = fma2(xv[2 * j + 1], e23, a1);
            }
            float2 sa = unpack2(add2(a0, a1));
            float dot = sa.x + sa.y;
            float d = fmaf(-2.0f, dot, en2s[e]);
            int ei = ch * 128 + e;
            bool c = d < best;
            best = c ? d : best;
            bi   = c ? ei : bi;
        }
    }

    // ---- Emit outputs ----
    out_enc[(size_t)(tbase + tid) * NUM_EMBED + bi] = 1.0f;
    atomicAdd(&g_counts[bi], 1.0f);

    const float4* q4 = reinterpret_cast<const float4*>(emb + bi * EMBED_DIM);
    float* op        = out_main + ((size_t)n << 18) + hw;
    float* dwp       = g_dw + bi * EMBED_DIM;

    float lsum = 0.0f;
#pragma unroll
    for (int j = 0; j < 16; ++j) {
        float2 x0 = unpack2(xv[2 * j]);
        float2 x1 = unpack2(xv[2 * j + 1]);
        float4 q = q4[j];
        // mirror reference exactly: out = x + (q - x) in fp32 (no folding)
        float d0 = __fsub_rn(q.x, x0.x);
        float d1 = __fsub_rn(q.y, x0.y);
        float d2 = __fsub_rn(q.z, x1.x);
        float d3 = __fsub_rn(q.w, x1.y);
        op[(4 * j)     << 12] = __fadd_rn(x0.x, d0);
        op[(4 * j + 1) << 12] = __fadd_rn(x0.y, d1);
        op[(4 * j + 2) << 12] = __fadd_rn(x1.x, d2);
        op[(4 * j + 3) << 12] = __fadd_rn(x1.y, d3);
        lsum += d0 * d0 + d1 * d1 + d2 * d2 + d3 * d3;
        red_add_v4(dwp + 4 * j, x0.x, x0.y, x1.x, x1.y);
    }

    // block-reduce loss partial
    red[tid] = lsum;
    __syncthreads();
#pragma unroll
    for (int o = 128; o > 0; o >>= 1) {
        if (tid < o) red[tid] += red[tid + o];
        __syncthreads();
    }
    if (tid == 0) atomicAdd(&g_loss, red[0]);
}

// ============================================================
// Phase 2a: scalar finalize — cluster, k, perplexity, loss.
// One block, 512 threads. Re-zeros g_counts/g_loss after use.
// ============================================================
__global__ void vq_phase2a(const float* __restrict__ ema_cs,
                           float* __restrict__ dout) {
    __shared__ float s[512];
    int e = threadIdx.x;

    float cnt = g_counts[e];
    g_counts[e] = 0.0f;                       // recycle for next replay
    float cl = ema_cs[e] * DECAY + ONE_MINUS_DECAY * cnt;

    s[e] = cl;
    __syncthreads();
    for (int o = 256; o > 0; o >>= 1) {
        if (e < o) s[e] += s[e + o];
        __syncthreads();
    }
    float k = s[0];
    __syncthreads();

    float cls = (cl + EPS) / (k + NUM_EMBED * EPS) * k;
    dout[OFF_CLUST + e] = cls;
    g_cls[e] = cls;

    float p = cnt * (1.0f / (float)N_TOKENS);
    float t = -p * logf(p + 1e-10f);
    s[e] = t;
    __syncthreads();
    for (int o = 256; o > 0; o >>= 1) {
        if (e < o) s[e] += s[e + o];
        __syncthreads();
    }
    if (e == 0) {
        dout[OFF_PERP] = expf(s[0]);
        dout[OFF_LOSS] = COMMIT_COST * (g_loss / 8388608.0f);
        g_loss = 0.0f;                        // recycle
    }
}

// ============================================================
// Phase 2b: EMA rows, fully parallel. 64 blocks x 512 threads,
// one element each. Re-zeros g_dw after use.
// ============================================================
__global__ void vq_phase2b(const float* __restrict__ ema_w,
                           float* __restrict__ dout) {
    int gid = blockIdx.x * 512 + threadIdx.x;   // 0..32767
    int row = gid >> 6;                         // code index

    float d = g_dw[gid];
    g_dw[gid] = 0.0f;                           // recycle for next replay
    float w = ema_w[gid] * DECAY + ONE_MINUS_DECAY * d;
    dout[OFF_EMAW + gid] = w;
    dout[OFF_NEMB + gid] = w / g_cls[row];
}

// ============================================================
extern "C" void kernel_launch(void* const* d_in, const int* in_sizes, int n_in,
                              void* d_out, int out_size) {
    const float* x      = (const float*)d_in[0];
    const float* emb    = (const float*)d_in[1];
    const float* ema_w  = (const float*)d_in[2];
    const float* ema_cs = (const float*)d_in[3];
    float* dout = (float*)d_out;

    vq_phase0<<<1, 512>>>(emb);
    vq_phase1<<<512, 256>>>(x, emb, dout);
    vq_phase2a<<<1, 512>>>(ema_cs, dout);
    vq_phase2b<<<64, 512>>>(ema_w, dout);
}

// round 16
// speedup vs baseline: 1.0319x; 1.0319x over previous
#include <cuda_runtime.h>
#include <cuda_bf16.h>
#include <cfloat>
#include <cstdint>

#define NUM_EMBED 512
#define EMBED_DIM 64
#define N_TOKENS  131072
#define DECAY     0.99f
#define ONE_MINUS_DECAY 0.01f
#define EPS       1e-5f
#define COMMIT_COST 0.25f

#define OFF_LOSS   0
#define OFF_OUT    1
#define OFF_PERP   8388609
#define OFF_ENC    8388610
#define OFF_NEMB   75497474ll
#define OFF_CLUST  75530242ll
#define OFF_EMAW   75530754ll

// Scratch. INVARIANT: g_counts/g_loss/g_dw zero at kernel_launch entry
// (zeroed at load; phase2a/2b re-zero after consuming).
__device__ float               g_counts[NUM_EMBED];
__device__ __align__(16) float g_dw[NUM_EMBED * EMBED_DIM];
__device__ float               g_en2[NUM_EMBED];
__device__ float               g_cls[NUM_EMBED];
__device__ float               g_loss;
// bf16 split codebook (hi/lo), K-major rows of 64
__device__ __align__(16) __nv_bfloat16 g_ebh[NUM_EMBED * EMBED_DIM];
__device__ __align__(16) __nv_bfloat16 g_ebl[NUM_EMBED * EMBED_DIM];

typedef unsigned long long ull;

// ---- f32x2 helpers (for the exact-chain fallback; bit-identical to R9) ----
__device__ __forceinline__ ull fma2(ull a, ull b, ull c) {
    ull d; asm("fma.rn.f32x2 %0, %1, %2, %3;" : "=l"(d) : "l"(a), "l"(b), "l"(c)); return d;
}
__device__ __forceinline__ ull add2(ull a, ull b) {
    ull d; asm("add.rn.f32x2 %0, %1, %2;" : "=l"(d) : "l"(a), "l"(b)); return d;
}
__device__ __forceinline__ ull pack2(float lo, float hi) {
    ull d; asm("mov.b64 %0, {%1, %2};" : "=l"(d) : "f"(lo), "f"(hi)); return d;
}
__device__ __forceinline__ float2 unpack2(ull v) {
    float2 r; asm("mov.b64 {%0, %1}, %2;" : "=f"(r.x), "=f"(r.y) : "l"(v)); return r;
}
__device__ __forceinline__ void red_add_v4(float* p, float a, float b, float c, float d) {
    asm volatile("red.global.add.v4.f32 [%0], {%1,%2,%3,%4};"
                 :: "l"(p), "f"(a), "f"(b), "f"(c), "f"(d) : "memory");
}
__device__ __forceinline__ uint32_t smem_to_u32(const void* p) {
    uint32_t a;
    asm("{ .reg .u64 t; cvta.to.shared.u64 t, %1; cvt.u32.u64 %0, t; }" : "=r"(a) : "l"(p));
    return a;
}

// ---- warp MMA primitives (base-target legal: sm_80+) ----
__device__ __forceinline__ void ldsm_x4(uint32_t* r, uint32_t addr) {
    asm volatile("ldmatrix.sync.aligned.m8n8.x4.shared.b16 {%0,%1,%2,%3}, [%4];"
                 : "=r"(r[0]), "=r"(r[1]), "=r"(r[2]), "=r"(r[3]) : "r"(addr));
}
__device__ __forceinline__ void mma_bf16(float* c, const uint32_t* a, const uint32_t* b) {
    asm volatile("mma.sync.aligned.m16n8k16.row.col.f32.bf16.bf16.f32 "
                 "{%0,%1,%2,%3}, {%4,%5,%6,%7}, {%8,%9}, {%0,%1,%2,%3};"
                 : "+f"(c[0]), "+f"(c[1]), "+f"(c[2]), "+f"(c[3])
                 : "r"(a[0]), "r"(a[1]), "r"(a[2]), "r"(a[3]), "r"(b[0]), "r"(b[1]));
}

#define TILE_STRIDE 144            // 72 bf16 per row (16B-aligned, bank-rotating)
#define TILE_BYTES  (128 * TILE_STRIDE)   // 18432 per split
#define MARGIN 4e-3f

// ============================================================
// Phase 0: ||e||^2 (expression VERBATIM — argmin-tie-critical) + bf16 split.
// ============================================================
__global__ void vq_phase0(const float* __restrict__ emb) {
    int tid = threadIdx.x;                          // one code per thread (512)
    const float2* ep = reinterpret_cast<const float2*>(emb + tid * EMBED_DIM);
    float s = 0.0f;
    unsigned* oh = reinterpret_cast<unsigned*>(g_ebh) + tid * 32;
    unsigned* ol = reinterpret_cast<unsigned*>(g_ebl) + tid * 32;
#pragma unroll
    for (int j = 0; j < 32; ++j) {
        float2 v = ep[j];
        s += v.x * v.x + v.y * v.y;
        __nv_bfloat16 h0 = __float2bfloat16(v.x);
        __nv_bfloat16 h1 = __float2bfloat16(v.y);
        __nv_bfloat16 l0 = __float2bfloat16(v.x - __bfloat162float(h0));
        __nv_bfloat16 l1 = __float2bfloat16(v.y - __bfloat162float(h1));
        oh[j] = (unsigned)__bfloat16_as_ushort(h0) | ((unsigned)__bfloat16_as_ushort(h1) << 16);
        ol[j] = (unsigned)__bfloat16_as_ushort(l0) | ((unsigned)__bfloat16_as_ushort(l1) << 16);
    }
    g_en2[tid] = s;
}

// ============================================================
// Phase 1: HMMA approx distances + certified argmin + fused epilogue.
// 1024 blocks x 128 threads (4 warps), one token per thread.
// ============================================================
__global__ void __launch_bounds__(128)
vq_phase1(const float* __restrict__ x,
          const float* __restrict__ emb,
          float* __restrict__ dout) {
    __shared__ __align__(16) unsigned char s_tile[2 * TILE_BYTES]; // hi | lo
    __shared__ float s_en2[NUM_EMBED];
    __shared__ float s_red[128];
    __shared__ int   s_bi[128];
    __shared__ float s_b1[128];
    __shared__ float s_b2[128];

    const int tid  = threadIdx.x;
    const int lane = tid & 31;
    const int w    = tid >> 5;
    const int grp  = lane >> 3;      // ldmatrix address group
    const int r8   = lane & 7;
    const int tbase = blockIdx.x << 7;
    const int n     = tbase >> 12;
    const int hw    = (tbase & 4095) + tid;

    const uint32_t tile_u32 = smem_to_u32(s_tile);

    float* out_main = dout + OFF_OUT;
    float* out_enc  = dout + OFF_ENC;

    // Coalesced zero of this block's 128 encodings rows (256 KB) — early.
    {
        float2* ez = reinterpret_cast<float2*>(out_enc + (size_t)tbase * NUM_EMBED);
        float2 z2 = make_float2(0.0f, 0.0f);
#pragma unroll 8
        for (int i = tid; i < 128 * NUM_EMBED / 2; i += 128) ez[i] = z2;
    }
    for (int i = tid; i < NUM_EMBED; i += 128) s_en2[i] = g_en2[i];

    // ---- Stage x (token tid) as bf16 hi/lo rows into the tile ----
    const float* xp = x + ((size_t)n << 18) + hw;
    {
        unsigned* rh = reinterpret_cast<unsigned*>(s_tile + tid * TILE_STRIDE);
        unsigned* rl = reinterpret_cast<unsigned*>(s_tile + TILE_BYTES + tid * TILE_STRIDE);
#pragma unroll
        for (int j = 0; j < 32; ++j) {
            float f0 = xp[(2 * j) << 12];
            float f1 = xp[(2 * j + 1) << 12];
            __nv_bfloat16 h0 = __float2bfloat16(f0);
            __nv_bfloat16 h1 = __float2bfloat16(f1);
            __nv_bfloat16 l0 = __float2bfloat16(f0 - __bfloat162float(h0));
            __nv_bfloat16 l1 = __float2bfloat16(f1 - __bfloat162float(h1));
            rh[j] = (unsigned)__bfloat16_as_ushort(h0) | ((unsigned)__bfloat16_as_ushort(h1) << 16);
            rl[j] = (unsigned)__bfloat16_as_ushort(l0) | ((unsigned)__bfloat16_as_ushort(l1) << 16);
        }
    }
    __syncthreads();

    // ---- Load A fragments (rows w*32 .. w*32+31, all K) into registers ----
    // m16n8k16 A frag via ldmatrix x4: groups -> (r, k0-7), (r+8, k0-7), (r, k8-15), (r+8, k8-15)
    const int arow = r8 + (grp & 1) * 8;
    const int akof = (grp >> 1) * 8;
    uint32_t ah[2][4][4], al[2][4][4];
#pragma unroll
    for (int m = 0; m < 2; ++m)
#pragma unroll
        for (int k = 0; k < 4; ++k) {
            uint32_t ad = tile_u32 + (w * 32 + m * 16 + arow) * TILE_STRIDE + (k * 16 + akof) * 2;
            ldsm_x4(ah[m][k], ad);
            ldsm_x4(al[m][k], ad + TILE_BYTES);
        }
    __syncthreads();   // A is in regs; tile region reusable for B

    float tb1[4], tb2[4];
    int   ti1[4];
#pragma unroll
    for (int s = 0; s < 4; ++s) { tb1[s] = FLT_MAX; tb2[s] = FLT_MAX; ti1[s] = 0; }

    for (int ch = 0; ch < 4; ++ch) {
        // stage 128 codes (hi+lo) — thread tid owns code row tid
        {
            const uint4* sh = reinterpret_cast<const uint4*>(g_ebh + (size_t)(ch * 128 + tid) * 64);
            const uint4* sl = reinterpret_cast<const uint4*>(g_ebl + (size_t)(ch * 128 + tid) * 64);
            uint4* dh = reinterpret_cast<uint4*>(s_tile + tid * TILE_STRIDE);
            uint4* dl = reinterpret_cast<uint4*>(s_tile + TILE_BYTES + tid * TILE_STRIDE);
#pragma unroll
            for (int i = 0; i < 8; ++i) { dh[i] = sh[i]; dl[i] = sl[i]; }
        }
        __syncthreads();

#pragma unroll 2
        for (int nt = 0; nt < 16; ++nt) {
            // B frags: codes nt*8..+7, all K. No .trans needed (codes are k-contiguous).
            uint32_t baddr = tile_u32 + (nt * 8 + r8) * TILE_STRIDE + grp * 16;
            uint32_t bh01[4], bh23[4], bl01[4], bl23[4];
            ldsm_x4(bh01, baddr);                      // hi, k 0-31
            ldsm_x4(bh23, baddr + 64);                 // hi, k 32-63
            ldsm_x4(bl01, baddr + TILE_BYTES);         // lo, k 0-31
            ldsm_x4(bl23, baddr + TILE_BYTES + 64);    // lo, k 32-63

#pragma unroll
            for (int m = 0; m < 2; ++m) {
                float c[4] = {0.f, 0.f, 0.f, 0.f};
                // D = Ah*Bh + Ah*Bl + Al*Bh (xl*el dropped; margin covers)
                mma_bf16(c, ah[m][0], &bh01[0]); mma_bf16(c, ah[m][0], &bl01[0]); mma_bf16(c, al[m][0], &bh01[0]);
                mma_bf16(c, ah[m][1], &bh01[2]); mma_bf16(c, ah[m][1], &bl01[2]); mma_bf16(c, al[m][1], &bh01[2]);
                mma_bf16(c, ah[m][2], &bh23[0]); mma_bf16(c, ah[m][2], &bl23[0]); mma_bf16(c, al[m][2], &bh23[0]);
                mma_bf16(c, ah[m][3], &bh23[2]); mma_bf16(c, ah[m][3], &bl23[2]); mma_bf16(c, al[m][3], &bh23[2]);

                int code0 = ch * 128 + nt * 8 + (lane & 3) * 2;
                float e0 = s_en2[code0], e1 = s_en2[code0 + 1];
                float d00 = fmaf(-2.0f, c[0], e0);   // row r,   col code0
                float d01 = fmaf(-2.0f, c[1], e1);   // row r,   col code0+1
                float d10 = fmaf(-2.0f, c[2], e0);   // row r+8, col code0
                float d11 = fmaf(-2.0f, c[3], e1);   // row r+8, col code0+1
                int s0 = m * 2, s1 = m * 2 + 1;
                if (d00 < tb1[s0]) { tb2[s0] = tb1[s0]; tb1[s0] = d00; ti1[s0] = code0; }
                else if (d00 < tb2[s0]) tb2[s0] = d00;
                if (d01 < tb1[s0]) { tb2[s0] = tb1[s0]; tb1[s0] = d01; ti1[s0] = code0 + 1; }
                else if (d01 < tb2[s0]) tb2[s0] = d01;
                if (d10 < tb1[s1]) { tb2[s1] = tb1[s1]; tb1[s1] = d10; ti1[s1] = code0; }
                else if (d10 < tb2[s1]) tb2[s1] = d10;
                if (d11 < tb1[s1]) { tb2[s1] = tb1[s1]; tb1[s1] = d11; ti1[s1] = code0 + 1; }
                else if (d11 < tb2[s1]) tb2[s1] = d11;
            }
        }
        __syncthreads();   // B tile reuse safety
    }

    // ---- Cross-thread top-2 merge (quads hold the same row) ----
#pragma unroll
    for (int s = 0; s < 4; ++s) {
        float b1 = tb1[s], b2 = tb2[s]; int i1 = ti1[s];
#pragma unroll
        for (int off = 1; off < 4; off <<= 1) {
            float o1 = __shfl_down_sync(0xffffffffu, b1, off, 4);
            float o2 = __shfl_down_sync(0xffffffffu, b2, off, 4);
            int   oi = __shfl_down_sync(0xffffffffu, i1, off, 4);
            if (o1 < b1) { b2 = fminf(b1, o2); b1 = o1; i1 = oi; }
            else         { b2 = fminf(b2, o1); }
        }
        if ((lane & 3) == 0) {
            int row = w * 32 + (s >> 1) * 16 + (lane >> 2) + (s & 1) * 8;
            s_bi[row] = i1; s_b1[row] = b1; s_b2[row] = b2;
        }
    }
    __syncthreads();

    // ---- Per-token: certified winner or exact fp32 rescan (R9 chain) ----
    ull xv[32];
#pragma unroll
    for (int j = 0; j < 32; ++j)
        xv[j] = pack2(xp[(2 * j) << 12], xp[(2 * j + 1) << 12]);

    int bi = s_bi[tid];
    if (s_b2[tid] - s_b1[tid] < MARGIN) {
        float bb = FLT_MAX; int bbi = 0;
        for (int e = 0; e < NUM_EMBED; ++e) {
            const float4* ep = reinterpret_cast<const float4*>(emb + e * EMBED_DIM);
            ull a0 = 0, a1 = 0;
#pragma unroll
            for (int j = 0; j < 16; ++j) {
                float4 v = ep[j];
                a0 = fma2(xv[2 * j],     pack2(v.x, v.y), a0);
                a1 = fma2(xv[2 * j + 1], pack2(v.z, v.w), a1);
            }
            float2 sa = unpack2(add2(a0, a1));
            float dot = sa.x + sa.y;
            float d = fmaf(-2.0f, dot, s_en2[e]);
            if (d < bb) { bb = d; bbi = e; }
        }
        bi = bbi;
    }

    // ---- Epilogue (verbatim from proven kernel) ----
    out_enc[(size_t)(tbase + tid) * NUM_EMBED + bi] = 1.0f;
    atomicAdd(&g_counts[bi], 1.0f);

    const float4* q4 = reinterpret_cast<const float4*>(emb + bi * EMBED_DIM);
    float* op        = out_main + ((size_t)n << 18) + hw;
    float* dwp       = g_dw + bi * EMBED_DIM;

    float lsum = 0.0f;
#pragma unroll
    for (int j = 0; j < 16; ++j) {
        float2 x0 = unpack2(xv[2 * j]);
        float2 x1 = unpack2(xv[2 * j + 1]);
        float4 qv = q4[j];
        float d0 = __fsub_rn(qv.x, x0.x);
        float d1 = __fsub_rn(qv.y, x0.y);
        float d2 = __fsub_rn(qv.z, x1.x);
        float d3 = __fsub_rn(qv.w, x1.y);
        op[(4 * j)     << 12] = __fadd_rn(x0.x, d0);
        op[(4 * j + 1) << 12] = __fadd_rn(x0.y, d1);
        op[(4 * j + 2) << 12] = __fadd_rn(x1.x, d2);
        op[(4 * j + 3) << 12] = __fadd_rn(x1.y, d3);
        lsum += d0 * d0 + d1 * d1 + d2 * d2 + d3 * d3;
        red_add_v4(dwp + 4 * j, x0.x, x0.y, x1.x, x1.y);
    }

    s_red[tid] = lsum;
    __syncthreads();
#pragma unroll
    for (int o = 64; o > 0; o >>= 1) {
        if (tid < o) s_red[tid] += s_red[tid + o];
        __syncthreads();
    }
    if (tid == 0) atomicAdd(&g_loss, s_red[0]);
}

// ============================================================
// Phase 2a: cluster/k/perplexity/loss. 1 block x 512.
// ============================================================
__global__ void vq_phase2a(const float* __restrict__ ema_cs,
                           float* __restrict__ dout) {
    __shared__ float s[512];
    int e = threadIdx.x;
    float cnt = g_counts[e];
    g_counts[e] = 0.0f;
    float cl = ema_cs[e] * DECAY + ONE_MINUS_DECAY * cnt;
    s[e] = cl;
    __syncthreads();
    for (int o = 256; o > 0; o >>= 1) { if (e < o) s[e] += s[e + o]; __syncthreads(); }
    float k = s[0];
    __syncthreads();
    float cls = (cl + EPS) / (k + NUM_EMBED * EPS) * k;
    dout[OFF_CLUST + e] = cls;
    g_cls[e] = cls;
    float p = cnt * (1.0f / (float)N_TOKENS);
    float t = -p * logf(p + 1e-10f);
    s[e] = t;
    __syncthreads();
    for (int o = 256; o > 0; o >>= 1) { if (e < o) s[e] += s[e + o]; __syncthreads(); }
    if (e == 0) {
        dout[OFF_PERP] = expf(s[0]);
        dout[OFF_LOSS] = COMMIT_COST * (g_loss / 8388608.0f);
        g_loss = 0.0f;
    }
}

// ============================================================
// Phase 2b: EMA rows. 64 blocks x 512.
// ============================================================
__global__ void vq_phase2b(const float* __restrict__ ema_w,
                           float* __restrict__ dout) {
    int gid = blockIdx.x * 512 + threadIdx.x;
    int row = gid >> 6;
    float d = g_dw[gid];
    g_dw[gid] = 0.0f;
    float w = ema_w[gid] * DECAY + ONE_MINUS_DECAY * d;
    dout[OFF_EMAW + gid] = w;
    dout[OFF_NEMB + gid] = w / g_cls[row];
}

// ============================================================
extern "C" void kernel_launch(void* const* d_in, const int* in_sizes, int n_in,
                              void* d_out, int out_size) {
    const float* x      = (const float*)d_in[0];
    const float* emb    = (const float*)d_in[1];
    const float* ema_w  = (const float*)d_in[2];
    const float* ema_cs = (const float*)d_in[3];
    float* dout = (float*)d_out;

    vq_phase0<<<1, 512>>>(emb);
    vq_phase1<<<N_TOKENS / 128, 128>>>(x, emb, dout);
    vq_phase2a<<<1, 512>>>(ema_cs, dout);
    vq_phase2b<<<64, 512>>>(ema_w, dout);
}